// round 14
// baseline (speedup 1.0000x reference)
#include <cuda_runtime.h>
#include <cooperative_groups.h>
#include <cuda_bf16.h>
#include <math.h>
#include <stdint.h>

namespace cg = cooperative_groups;

#define T_STEPS  2000
#define BATCH    512
#define CLUSTER_N 4
#define NCLUSTERS 32
#define THREADS  512
#define BC       16      // batch rows per cluster

typedef unsigned long long ull;

// layer0 hidden sequence as PACKED words (bf16 hi | bf16 lo << 16), final h2
__device__ unsigned g_h1[(size_t)T_STEPS * BATCH * 128];
__device__ float g_h2last[BATCH * 128];

// ---------- activation approximations ----------
__device__ __forceinline__ float tanh_f(float x) {
    float y; asm("tanh.approx.f32 %0, %1;" : "=f"(y) : "f"(x)); return y;
}
__device__ __forceinline__ float sig_f(float x) {
    float e; asm("ex2.approx.f32 %0, %1;" : "=f"(e) : "f"(-1.4426950408889634f * x));
    float d = 1.0f + e, r;
    asm("rcp.approx.f32 %0, %1;" : "=f"(r) : "f"(d));
    return r;
}

// ---------- mbarrier / cluster helpers (R10/R13-proven) ----------
__device__ __forceinline__ void mbar_init(unsigned a, unsigned cnt) {
    asm volatile("mbarrier.init.shared.b64 [%0], %1;" :: "r"(a), "r"(cnt) : "memory");
}
__device__ __forceinline__ void mbar_arrive_rank(unsigned a, unsigned rk) {
    asm volatile(
        "{\n\t.reg .b32 ra;\n\t"
        "mapa.shared::cluster.u32 ra, %0, %1;\n\t"
        "mbarrier.arrive.release.cluster.shared::cluster.b64 _, [ra];\n\t}"
        :: "r"(a), "r"(rk) : "memory");
}
__device__ __forceinline__ void mbar_wait_cl(unsigned a, unsigned par) {
    asm volatile(
        "{\n\t.reg .pred P;\n\tLW%=:\n\t"
        "mbarrier.try_wait.parity.acquire.cluster.shared::cta.b64 P, [%0], %1, 0x989680;\n\t"
        "@P bra LD%=;\n\tbra LW%=;\n\tLD%=:\n\t}"
        :: "r"(a), "r"(par) : "memory");
}
__device__ __forceinline__ unsigned mapa_rk(unsigned a, unsigned rk) {
    unsigned r; asm("mapa.shared::cluster.u32 %0, %1, %2;" : "=r"(r) : "r"(a), "r"(rk));
    return r;
}
__device__ __forceinline__ void stc_u32(unsigned a, unsigned v) {
    asm volatile("st.shared::cluster.u32 [%0], %1;" :: "r"(a), "r"(v) : "memory");
}

// ---------- bf16 HMMA m16n8k16 (sm_80+ baseline PTX) ----------
__device__ __forceinline__ void mma_bf16(float* d, const unsigned* a, const unsigned* b) {
    asm volatile(
        "mma.sync.aligned.m16n8k16.row.col.f32.bf16.bf16.f32 "
        "{%0,%1,%2,%3}, {%4,%5,%6,%7}, {%8,%9}, {%0,%1,%2,%3};"
        : "+f"(d[0]), "+f"(d[1]), "+f"(d[2]), "+f"(d[3])
        : "r"(a[0]), "r"(a[1]), "r"(a[2]), "r"(a[3]), "r"(b[0]), "r"(b[1]));
}
__device__ __forceinline__ unsigned pack2(float x, float y) {
    __nv_bfloat162 v = __floats2bfloat162_rn(x, y);
    return *reinterpret_cast<unsigned*>(&v);
}
// pack one value as (hi | lo<<16); hi = bf16(v), lo = bf16(v - hi)
__device__ __forceinline__ unsigned pack_hilo(float v) {
    __nv_bfloat16 hb = __float2bfloat16(v);
    float hf = __bfloat162float(hb);
    __nv_bfloat16 lb = __float2bfloat16(v - hf);
    return (unsigned)__bfloat16_as_ushort(hb) | ((unsigned)__bfloat16_as_ushort(lb) << 16);
}

// =====================================================================
// Half-pipelined persistent LSTM scan. Cluster of 4 CTAs = 16 rows,
// split into halves H0 (rows 0-7) and H1 (rows 8-15): independent
// recurrences sharing W. Phase phi: GEMM(half = phi&1, t = phi>>1)
// overlapped (same warps, ILP) with pointwise(other half, t=(phi-1)>>1).
// CTA rank r owns gate-interleaved cols [32r,32r+32) of every gate ->
// pointwise fully local; h replicated to 4 peers as ONE packed u32.
// B tile: per-element interleaved hi/lo words; fragments split via PRMT.
// A (weights, hi/lo bf16) step-invariant in registers. Partials double-
// buffered by phase parity; B single-buffered (halves row-disjoint).
// One release/acquire cluster mbarrier per phase.
// =====================================================================
template<int K_IN, int K_PAD, int KS, bool IS_L0>
__global__ __launch_bounds__(THREADS, 1) __cluster_dims__(CLUSTER_N, 1, 1)
void lstm_scan(const float* __restrict__ W_ih, const float* __restrict__ W_hh,
               const float* __restrict__ b_ih, const float* __restrict__ b_hh,
               const float* __restrict__ x)
{
    constexpr int ROWB    = K_PAD * 4 + 16;        // bytes per B row (u32 words)
    constexpr int PSTR    = 130;                   // partial row stride (floats)
    constexpr int PARTBUF = 32 * PSTR;             // floats per buffer (4kq x 8n)
    constexpr int OPART   = BC * ROWB;
    constexpr int OBIAS   = OPART + 2 * PARTBUF * 4;
    constexpr int OMB     = OBIAS + 512;

    extern __shared__ char smraw[];
    char* base = (char*)(((uintptr_t)smraw + 127) & ~(uintptr_t)127);
    float* part   = (float*)(base + OPART);
    float* bias_s = (float*)(base + OBIAS);
    const unsigned base_u = (unsigned)__cvta_generic_to_shared(base);
    const unsigned mb_u   = base_u + OMB;

    cg::cluster_group cluster = cg::this_cluster();
    const int rank = (int)cluster.block_rank();
    const int tid  = threadIdx.x;
    const int warp = tid >> 5, lane = tid & 31;
    const int cid  = blockIdx.x / CLUSTER_N;
    const int B0   = cid * BC;

    const int lg = lane >> 2, la = lane & 3;       // mma groupID / threadInGroup
    const int mtp = warp & 3, kq = warp >> 2;      // m-pair, K-quarter

    // ---- one-time: weight fragments (hi/lo split) into registers (R13 map) ----
    unsigned Ahi[2][KS][4], Alo[2][KS][4];
    #pragma unroll
    for (int mt = 0; mt < 2; ++mt) {
        const int MT = mtp * 2 + mt;
        #pragma unroll
        for (int s = 0; s < KS; ++s) {
            const int kbase = (kq * KS + s) * 16;
            #pragma unroll
            for (int r = 0; r < 4; ++r) {
                int m = MT * 16 + lg + ((r & 1) ? 8 : 0);
                int k = kbase + la * 2 + ((r & 2) ? 8 : 0);
                int grow = (m >> 5) * 128 + 32 * rank + (m & 31);
                float v0 = 0.0f, v1 = 0.0f;
                if (k < 128) v0 = W_hh[grow * 128 + k];
                else if (k - 128 < K_IN) v0 = W_ih[grow * K_IN + (k - 128)];
                if (k + 1 < 128) v1 = W_hh[grow * 128 + k + 1];
                else if (k + 1 - 128 >= 0 && k + 1 - 128 < K_IN) v1 = W_ih[grow * K_IN + (k + 1 - 128)];
                float h0 = __bfloat162float(__float2bfloat16(v0));
                float h1 = __bfloat162float(__float2bfloat16(v1));
                Ahi[mt][s][r] = pack2(h0, h1);
                Alo[mt][s][r] = pack2(v0 - h0, v1 - h1);
            }
        }
    }

    // zero the whole B tile (h(0)=0, padding stays 0)
    for (int i = tid * 4; i < BC * ROWB; i += THREADS * 4)
        *(unsigned*)(base + i) = 0u;
    if (tid < 128) {
        int g = tid >> 5, c = tid & 31;
        bias_s[tid] = b_ih[g * 128 + 32 * rank + c] + b_hh[g * 128 + 32 * rank + c];
    }
    if (tid == 0) mbar_init(mb_u, 4);
    __syncthreads();

    unsigned peer_base[CLUSTER_N];
    #pragma unroll
    for (int d = 0; d < CLUSTER_N; ++d) peer_base[d] = mapa_rk(base_u, d);

    // pointwise (warps 0-7): row = half*8 + warp, col = lane within 32-slice
    float creg[2] = {0.0f, 0.0f};
    const float bi0 = bias_s[lane], bi1 = bias_s[32 + lane],
                bi2 = bias_s[64 + lane], bi3 = bias_s[96 + lane];

    // staging (warps 8-15): u in [0,256)
    const int u = tid - 256;
    int srow = 0, scol = 0;
    if constexpr (IS_L0) { srow = (u >= 0) ? u / 13 : 0; scol = (u >= 0) ? u - srow * 13 : 0; }
    else { srow = (u >= 0) ? (u >> 5) : 0; scol = (u >= 0) ? ((u & 31) * 4) : 0; }

    float pf_f = 0.0f; uint4 pf_u = {0,0,0,0};
    auto prefetch = [&](int half, int t) {       // warps 8-15 only
        if constexpr (IS_L0) {
            if (u < 104)
                pf_f = x[((size_t)(B0 + half * 8 + srow) * T_STEPS + t) * 13 + scol];
        } else {
            pf_u = *reinterpret_cast<const uint4*>(
                &g_h1[((size_t)t * BATCH + B0 + half * 8 + srow) * 128 + scol]);
        }
    };
    auto stage = [&](int half) {                 // warps 8-15 only
        if constexpr (IS_L0) {
            if (u < 104)
                *(unsigned*)(base + (half * 8 + srow) * ROWB + (128 + scol) * 4) = pack_hilo(pf_f);
        } else {
            *reinterpret_cast<uint4*>(base + (half * 8 + srow) * ROWB + (128 + scol) * 4) = pf_u;
        }
    };

    // prologue: stage H0(t0); preload for phase 0's staging of H1(t0)
    if (warp >= 8) { prefetch(0, 0); stage(0); prefetch(1, 0); }
    __syncthreads();
    cluster.sync();

    const int PH_MAX = 2 * T_STEPS;
    for (int phi = 0; phi <= PH_MAX; ++phi) {
        const int tg    = phi >> 1;
        const int ghalf = phi & 1;
        const int phalf = ghalf ^ 1;
        const int tp    = (phi - 1) >> 1;
        const bool do_g = (tg < T_STEPS);

        // ---- A) GEMM issue: D[128][8] for half ghalf ----
        float acc[2][4];
        if (do_g) {
            #pragma unroll
            for (int mt = 0; mt < 2; ++mt)
                #pragma unroll
                for (int r = 0; r < 4; ++r) acc[mt][r] = 0.0f;
            const char* Brow = base + (ghalf * 8 + lg) * ROWB;
            #pragma unroll
            for (int s = 0; s < KS; ++s) {
                const int kb = (kq * KS + s) * 16;
                const char* pb = Brow + (kb + la * 2) * 4;
                uint2 w0 = *(const uint2*)(pb);
                uint2 w1 = *(const uint2*)(pb + 32);
                unsigned bh[2], bl[2];
                bh[0] = __byte_perm(w0.x, w0.y, 0x5410);
                bl[0] = __byte_perm(w0.x, w0.y, 0x7632);
                bh[1] = __byte_perm(w1.x, w1.y, 0x5410);
                bl[1] = __byte_perm(w1.x, w1.y, 0x7632);
                #pragma unroll
                for (int mt = 0; mt < 2; ++mt) {
                    mma_bf16(acc[mt], Ahi[mt][s], bh);
                    mma_bf16(acc[mt], Ahi[mt][s], bl);
                    mma_bf16(acc[mt], Alo[mt][s], bh);
                }
            }
        }

        // ---- B) overlap work: pointwise (warps 0-7) / staging (warps 8-15) ----
        if (warp >= 8) {
            if (((phi + 1) >> 1) < T_STEPS) stage(phalf);
            const int tsn = (phi + 2) >> 1;
            if (tsn < T_STEPS) prefetch(ghalf, tsn);
        } else if (phi >= 1) {
            const float* pbq = part + ((phi & 1) ^ 1) * PARTBUF + warp * PSTR + lane;
            float g0 = bi0, g1 = bi1, g2 = bi2, g3 = bi3;
            #pragma unroll
            for (int q = 0; q < 4; ++q) {
                const float* pp = pbq + q * (8 * PSTR);
                g0 += pp[0]; g1 += pp[32]; g2 += pp[64]; g3 += pp[96];
            }
            float c = sig_f(g1) * creg[phalf] + sig_f(g0) * tanh_f(g2);
            creg[phalf] = c;
            float h = sig_f(g3) * tanh_f(c);
            unsigned word = pack_hilo(h);
            if (tp + 1 < T_STEPS) {
                const unsigned off = (unsigned)((phalf * 8 + warp) * ROWB + (32 * rank + lane) * 4);
                #pragma unroll
                for (int d = 0; d < CLUSTER_N; ++d) stc_u32(peer_base[d] + off, word);
            }
            if constexpr (IS_L0) {
                g_h1[((size_t)tp * BATCH + B0 + phalf * 8 + warp) * 128 + 32 * rank + lane] = word;
            } else {
                if (tp == T_STEPS - 1)
                    g_h2last[(B0 + phalf * 8 + warp) * 128 + 32 * rank + lane] = h;
            }
        }

        // ---- C) store GEMM partials (waits HMMA drain; B filled the window) ----
        if (do_g) {
            float* pq = part + (phi & 1) * PARTBUF + kq * (8 * PSTR);
            #pragma unroll
            for (int mt = 0; mt < 2; ++mt) {
                const int m0 = (mtp * 2 + mt) * 16 + lg;
                pq[(2 * la) * PSTR + m0]         = acc[mt][0];
                pq[(2 * la + 1) * PSTR + m0]     = acc[mt][1];
                pq[(2 * la) * PSTR + m0 + 8]     = acc[mt][2];
                pq[(2 * la + 1) * PSTR + m0 + 8] = acc[mt][3];
            }
        }

        // ---- D) phase barrier ----
        if (phi < PH_MAX) {
            __syncthreads();
            if (phi < PH_MAX - 1) {
                if (tid < 4) mbar_arrive_rank(mb_u, (unsigned)tid);
                mbar_wait_cl(mb_u, (unsigned)(phi & 1));
            }
        }
    }

    cluster.sync();   // keep SMEM alive for any in-flight peer stores
}

__global__ void fc_kernel(const float* __restrict__ Wfc, const float* __restrict__ bfc,
                          float* __restrict__ out)
{
    __shared__ float w[4][128];
    int tid = threadIdx.x;
    for (int idx = tid; idx < 512; idx += 128) w[idx >> 7][idx & 127] = Wfc[idx];
    __syncthreads();
    int b = blockIdx.x * 128 + tid;
    float s[4];
    #pragma unroll
    for (int cc = 0; cc < 4; ++cc) s[cc] = bfc[cc];
    #pragma unroll 4
    for (int k = 0; k < 128; ++k) {
        float h = g_h2last[b * 128 + k];
        #pragma unroll
        for (int cc = 0; cc < 4; ++cc) s[cc] = fmaf(h, w[cc][k], s[cc]);
    }
    #pragma unroll
    for (int cc = 0; cc < 4; ++cc) out[b * 4 + cc] = s[cc];
}

extern "C" void kernel_launch(void* const* d_in, const int* in_sizes, int n_in,
                              void* d_out, int out_size)
{
    (void)in_sizes; (void)n_in; (void)out_size;
    const float* x    = (const float*)d_in[0];
    const float* Wih0 = (const float*)d_in[1];
    const float* Whh0 = (const float*)d_in[2];
    const float* bih0 = (const float*)d_in[3];
    const float* bhh0 = (const float*)d_in[4];
    const float* Wih1 = (const float*)d_in[5];
    const float* Whh1 = (const float*)d_in[6];
    const float* bih1 = (const float*)d_in[7];
    const float* bhh1 = (const float*)d_in[8];
    const float* Wfc  = (const float*)d_in[9];
    const float* bfc  = (const float*)d_in[10];
    float* out = (float*)d_out;

    // layer0: K_PAD=192 (h 0..127, x 128..140, zero pad), KS=3
    // layer1: K_PAD=256 (h2 0..127, h1 128..255),         KS=4
    auto smem_bytes = [](int kpad) {
        int rowb = kpad * 4 + 16;
        return BC * rowb + 2 * (32 * 130) * 4 + 512 + 16 + 256;
    };
    const int smem0 = smem_bytes(192);
    const int smem1 = smem_bytes(256);

    cudaFuncSetAttribute((const void*)lstm_scan<13, 192, 3, true>,
                         cudaFuncAttributeMaxDynamicSharedMemorySize, smem0);
    cudaFuncSetAttribute((const void*)lstm_scan<128, 256, 4, false>,
                         cudaFuncAttributeMaxDynamicSharedMemorySize, smem1);

    lstm_scan<13, 192, 3, true><<<NCLUSTERS * CLUSTER_N, THREADS, smem0>>>(
        Wih0, Whh0, bih0, bhh0, x);
    lstm_scan<128, 256, 4, false><<<NCLUSTERS * CLUSTER_N, THREADS, smem1>>>(
        Wih1, Whh1, bih1, bhh1, nullptr);
    fc_kernel<<<4, 128>>>(Wfc, bfc, out);
}

// round 15
// speedup vs baseline: 1.1789x; 1.1789x over previous
#include <cuda_runtime.h>
#include <cooperative_groups.h>
#include <cuda_bf16.h>
#include <stdint.h>

namespace cg = cooperative_groups;

#define T_STEPS  2000
#define BATCH    512
#define CLUSTER_N 4
#define THREADS  512
#define BCL      32     // batch rows per cluster
#define NCL      16     // clusters per layer
#define PSTR     132    // partial row stride (words); 2*PSTR%32==8 -> conflict-free STS

typedef unsigned long long ull;

// layer0 hidden sequence as packed words (bf16 hi | bf16 lo << 16)
__device__ unsigned g_h1[(size_t)T_STEPS * BATCH * 128];
__device__ float    g_h2last[BATCH * 128];
__device__ int      g_flags[NCL];   // producer progress counters (4 per step)

// ---------- activations ----------
__device__ __forceinline__ float tanh_f(float x){float y;asm("tanh.approx.f32 %0,%1;":"=f"(y):"f"(x));return y;}
__device__ __forceinline__ float sig_f(float x){ return 0.5f*tanh_f(0.5f*x) + 0.5f; }

// ---------- mbarrier / cluster helpers (R10/R13-proven) ----------
__device__ __forceinline__ void mbar_init(unsigned a, unsigned cnt) {
    asm volatile("mbarrier.init.shared.b64 [%0], %1;" :: "r"(a), "r"(cnt) : "memory");
}
__device__ __forceinline__ void mbar_arrive_rank(unsigned a, unsigned rk) {
    asm volatile(
        "{\n\t.reg .b32 ra;\n\t"
        "mapa.shared::cluster.u32 ra, %0, %1;\n\t"
        "mbarrier.arrive.release.cluster.shared::cluster.b64 _, [ra];\n\t}"
        :: "r"(a), "r"(rk) : "memory");
}
__device__ __forceinline__ void mbar_wait_cl(unsigned a, unsigned par) {
    asm volatile(
        "{\n\t.reg .pred P;\n\tLW%=:\n\t"
        "mbarrier.try_wait.parity.acquire.cluster.shared::cta.b64 P, [%0], %1, 0x989680;\n\t"
        "@P bra LD%=;\n\tbra LW%=;\n\tLD%=:\n\t}"
        :: "r"(a), "r"(par) : "memory");
}
__device__ __forceinline__ unsigned mapa_rk(unsigned a, unsigned rk) {
    unsigned r; asm("mapa.shared::cluster.u32 %0, %1, %2;" : "=r"(r) : "r"(a), "r"(rk));
    return r;
}
__device__ __forceinline__ void stc_u32(unsigned a, unsigned v) {
    asm volatile("st.shared::cluster.u32 [%0], %1;" :: "r"(a), "r"(v) : "memory");
}
__device__ __forceinline__ int ld_acq(const int* p) {
    int v; asm volatile("ld.acquire.gpu.global.b32 %0, [%1];" : "=r"(v) : "l"(p) : "memory");
    return v;
}

// ---------- bf16 HMMA m16n8k16 ----------
__device__ __forceinline__ void mma_bf16(float* d, const unsigned* a, const unsigned* b) {
    asm volatile(
        "mma.sync.aligned.m16n8k16.row.col.f32.bf16.bf16.f32 "
        "{%0,%1,%2,%3}, {%4,%5,%6,%7}, {%8,%9}, {%0,%1,%2,%3};"
        : "+f"(d[0]), "+f"(d[1]), "+f"(d[2]), "+f"(d[3])
        : "r"(a[0]), "r"(a[1]), "r"(a[2]), "r"(a[3]), "r"(b[0]), "r"(b[1]));
}
__device__ __forceinline__ unsigned pack2(float x, float y) {
    __nv_bfloat162 v = __floats2bfloat162_rn(x, y);
    return *reinterpret_cast<unsigned*>(&v);
}
__device__ __forceinline__ unsigned pack_hilo(float v) {
    __nv_bfloat16 hb = __float2bfloat16(v);
    float hf = __bfloat162float(hb);
    __nv_bfloat16 lb = __float2bfloat16(v - hf);
    return (unsigned)__bfloat16_as_ushort(hb) | ((unsigned)__bfloat16_as_ushort(lb) << 16);
}

// =====================================================================
// One cluster of 4 CTAs = 32 batch rows of ONE layer. CTA rank r owns
// gate-interleaved cols [32r,32r+32) of every gate -> pointwise local;
// h replicated to peers as one packed u32 via DSMEM.
// B row layout (u32 words): [h parity0: 128][h parity1: 128]
//                           [input parity0: IN_W][input parity1: IN_W]
// Fully parity-double-buffered -> peer pushes are skew-proof.
// GEMM: D[128][32] bf16 HMMA, 3-pass split precision, A in registers.
// 16 warps = 4 m-pairs x 4 K-quarters; partials combined in pointwise.
// Layer coupling: L0 stores packed h1 to gmem, fence, flag++ per CTA;
// L1 polls flags[lcid] >= 4*(s+1) before prefetching h1(s).
// =====================================================================
template<int K_IN, int K_PAD, int KS, bool IS_L0>
__device__ void scan_body(int lcid, char* base,
                          const float* __restrict__ W_ih, const float* __restrict__ W_hh,
                          const float* __restrict__ b_ih, const float* __restrict__ b_hh,
                          const float* __restrict__ x, cg::cluster_group& cluster)
{
    constexpr int IN_W  = K_PAD - 128;
    constexpr int RW    = 256 + 2 * IN_W;          // words per B row
    constexpr int ROWB  = RW * 4 + 16;             // bytes per B row
    constexpr int OPART = BCL * ROWB;
    constexpr int OBIAS = OPART + 4 * BCL * PSTR * 4;
    constexpr int OMB   = OBIAS + 512;

    float* part   = (float*)(base + OPART);
    float* bias_s = (float*)(base + OBIAS);
    const unsigned base_u = (unsigned)__cvta_generic_to_shared(base);
    const unsigned mb_u   = base_u + OMB;

    const int rank = (int)cluster.block_rank();
    const int tid  = threadIdx.x;
    const int warp = tid >> 5, lane = tid & 31;
    const int lg = lane >> 2, la = lane & 3;
    const int mtp = warp & 3, kq = warp >> 2;
    const int B0 = lcid * BCL;

    // ---- one-time: weight fragments (hi/lo) into registers ----
    unsigned Ahi[2][KS][4], Alo[2][KS][4];
    #pragma unroll
    for (int mt = 0; mt < 2; ++mt) {
        const int MT = mtp * 2 + mt;
        #pragma unroll
        for (int s = 0; s < KS; ++s) {
            const int kbase = (kq * KS + s) * 16;
            #pragma unroll
            for (int r = 0; r < 4; ++r) {
                int m = MT * 16 + lg + ((r & 1) ? 8 : 0);
                int k = kbase + la * 2 + ((r & 2) ? 8 : 0);
                int grow = (m >> 5) * 128 + 32 * rank + (m & 31);
                float v0 = 0.0f, v1 = 0.0f;
                if (k < 128) v0 = W_hh[grow * 128 + k];
                else if (k - 128 < K_IN) v0 = W_ih[grow * K_IN + (k - 128)];
                if (k + 1 < 128) v1 = W_hh[grow * 128 + k + 1];
                else if (k + 1 - 128 < K_IN) v1 = W_ih[grow * K_IN + (k + 1 - 128)];
                float h0 = __bfloat162float(__float2bfloat16(v0));
                float h1 = __bfloat162float(__float2bfloat16(v1));
                Ahi[mt][s][r] = pack2(h0, h1);
                Alo[mt][s][r] = pack2(v0 - h0, v1 - h1);
            }
        }
    }

    for (int i = tid * 4; i < BCL * ROWB; i += THREADS * 4)
        *(unsigned*)(base + i) = 0u;
    if (tid < 128) {
        int g = tid >> 5, c = tid & 31;
        bias_s[tid] = b_ih[g * 128 + 32 * rank + c] + b_hh[g * 128 + 32 * rank + c];
    }
    if (tid == 0) mbar_init(mb_u, 4);
    __syncthreads();
    cluster.sync();                                  // mbarriers visible

    unsigned peer_base[CLUSTER_N];
    #pragma unroll
    for (int d = 0; d < CLUSTER_N; ++d) peer_base[d] = mapa_rk(base_u, d);

    // pointwise ids: element rows pb_ and pb_+16, col jj
    const int pb_ = tid >> 5, jj = tid & 31;
    float creg0 = 0.0f, creg1 = 0.0f;
    const float bi0 = bias_s[jj], bi1 = bias_s[32 + jj],
                bi2 = bias_s[64 + jj], bi3 = bias_s[96 + jj];

    // staging ids
    int srow, scol;
    if constexpr (IS_L0) { srow = tid / 13; scol = tid - srow * 13; }
    else                 { srow = tid >> 4; scol = (tid & 15) * 8; }

    float pf_f = 0.0f; uint4 pfa = {0,0,0,0}, pfb = {0,0,0,0};
    auto prefetch = [&](int t) {
        if constexpr (IS_L0) {
            if (tid < BCL * 13)
                pf_f = x[((size_t)(B0 + srow) * T_STEPS + t) * 13 + scol];
        } else {
            const unsigned* src = &g_h1[((size_t)t * BATCH + B0 + srow) * 128 + scol];
            pfa = *(const uint4*)src; pfb = *(const uint4*)(src + 4);
        }
    };
    auto stage = [&](int pbuf) {
        if constexpr (IS_L0) {
            if (tid < BCL * 13)
                *(unsigned*)(base + srow * ROWB + (256 + IN_W * pbuf + scol) * 4) = pack_hilo(pf_f);
        } else {
            char* dst = base + srow * ROWB + (256 + IN_W * pbuf + scol) * 4;
            *(uint4*)dst = pfa; *(uint4*)(dst + 16) = pfb;
        }
    };

    // prologue: L1 waits for h1(0), h1(1)
    if constexpr (!IS_L0) {
        if (tid == 0) { while (ld_acq(&g_flags[lcid]) < 8) __nanosleep(64); }
        __syncthreads();
    }
    prefetch(0);
    stage(0);
    __syncthreads();

    for (int t = 0; t < T_STEPS; ++t) {
        const int p = t & 1;
        if (t + 1 < T_STEPS) prefetch(t + 1);

        // ---- GEMM: 3-pass split-precision bf16 HMMA, N=32 ----
        float acc[2][4][4];
        #pragma unroll
        for (int i = 0; i < 2; ++i)
            #pragma unroll
            for (int j = 0; j < 4; ++j)
                #pragma unroll
                for (int r = 0; r < 4; ++r) acc[i][j][r] = 0.0f;

        #pragma unroll
        for (int s = 0; s < KS; ++s) {
            const int k0 = (kq * KS + s) * 16;
            const int w0 = (k0 < 128) ? (k0 + 128 * p) : (256 + IN_W * p + (k0 - 128));
            const int bo = (w0 + la * 2) * 4;
            #pragma unroll
            for (int nt = 0; nt < 4; ++nt) {
                const char* Brow = base + (nt * 8 + lg) * ROWB + bo;
                uint2 q0 = *(const uint2*)(Brow);
                uint2 q1 = *(const uint2*)(Brow + 32);
                unsigned bh[2], bl[2];
                bh[0] = __byte_perm(q0.x, q0.y, 0x5410);
                bl[0] = __byte_perm(q0.x, q0.y, 0x7632);
                bh[1] = __byte_perm(q1.x, q1.y, 0x5410);
                bl[1] = __byte_perm(q1.x, q1.y, 0x7632);
                #pragma unroll
                for (int mt = 0; mt < 2; ++mt) {
                    mma_bf16(acc[mt][nt], Ahi[mt][s], bh);
                    mma_bf16(acc[mt][nt], Ahi[mt][s], bl);
                    mma_bf16(acc[mt][nt], Alo[mt][s], bh);
                }
            }
        }

        // store partials (PSTR=132 -> conflict-free)
        {
            float* pq = part + kq * (BCL * PSTR);
            #pragma unroll
            for (int mt = 0; mt < 2; ++mt) {
                const int m0 = (mtp * 2 + mt) * 16 + lg;
                #pragma unroll
                for (int nt = 0; nt < 4; ++nt) {
                    const int n0 = nt * 8 + 2 * la;
                    pq[n0 * PSTR + m0]           = acc[mt][nt][0];
                    pq[(n0 + 1) * PSTR + m0]     = acc[mt][nt][1];
                    pq[n0 * PSTR + m0 + 8]       = acc[mt][nt][2];
                    pq[(n0 + 1) * PSTR + m0 + 8] = acc[mt][nt][3];
                }
            }
        }
        if (t + 1 < T_STEPS) stage(p ^ 1);   // input(t+1) -> parity p^1 (disjoint)
        __syncthreads();

        // ---- pointwise: 2 elements per thread, fully CTA-local ----
        const int pn = p ^ 1;
        #pragma unroll
        for (int e = 0; e < 2; ++e) {
            const int r = pb_ + 16 * e;
            float g0 = bi0, g1 = bi1, g2 = bi2, g3 = bi3;
            #pragma unroll
            for (int q = 0; q < 4; ++q) {
                const float* pp = part + q * (BCL * PSTR) + r * PSTR + jj;
                g0 += pp[0]; g1 += pp[32]; g2 += pp[64]; g3 += pp[96];
            }
            float& cr = e ? creg1 : creg0;
            float c = sig_f(g1) * cr + sig_f(g0) * tanh_f(g2);
            cr = c;
            float h = sig_f(g3) * tanh_f(c);
            unsigned word = pack_hilo(h);
            if (t + 1 < T_STEPS) {
                const unsigned off = (unsigned)(r * ROWB + (128 * pn + 32 * rank + jj) * 4);
                #pragma unroll
                for (int d = 0; d < CLUSTER_N; ++d) stc_u32(peer_base[d] + off, word);
            }
            if constexpr (IS_L0) {
                g_h1[((size_t)t * BATCH + B0 + r) * 128 + 32 * rank + jj] = word;
            } else {
                if (t == T_STEPS - 1)
                    g_h2last[(B0 + r) * 128 + 32 * rank + jj] = h;
            }
        }

        if constexpr (IS_L0) __threadfence();                 // publish h1(t)
        if constexpr (!IS_L0) {
            if (tid == 0 && t + 2 < T_STEPS) {                // guard prefetch(t+2)
                const int tgt = 4 * (t + 3);
                while (ld_acq(&g_flags[lcid]) < tgt) __nanosleep(64);
            }
        }
        __syncthreads();
        if constexpr (IS_L0) { if (tid == 0) atomicAdd(&g_flags[lcid], 1); }

        if (t + 1 < T_STEPS) {
            if (tid < 4) mbar_arrive_rank(mb_u, (unsigned)tid);
            mbar_wait_cl(mb_u, (unsigned)(t & 1));
        }
    }
    cluster.sync();   // keep SMEM alive for in-flight peer stores
}

__global__ __launch_bounds__(THREADS, 1) __cluster_dims__(CLUSTER_N, 1, 1)
void lstm_fused(const float* __restrict__ x,
                const float* __restrict__ Wih0, const float* __restrict__ Whh0,
                const float* __restrict__ bih0, const float* __restrict__ bhh0,
                const float* __restrict__ Wih1, const float* __restrict__ Whh1,
                const float* __restrict__ bih1, const float* __restrict__ bhh1)
{
    extern __shared__ char smraw[];
    char* base = (char*)(((uintptr_t)smraw + 127) & ~(uintptr_t)127);
    cg::cluster_group cluster = cg::this_cluster();
    const int cid = blockIdx.x / CLUSTER_N;
    if (cid < NCL)
        scan_body<13, 192, 3, true >(cid,       base, Wih0, Whh0, bih0, bhh0, x,       cluster);
    else
        scan_body<128, 256, 4, false>(cid - NCL, base, Wih1, Whh1, bih1, bhh1, nullptr, cluster);
}

__global__ void zero_flags_kernel() {
    if (threadIdx.x < NCL) g_flags[threadIdx.x] = 0;
}

__global__ void fc_kernel(const float* __restrict__ Wfc, const float* __restrict__ bfc,
                          float* __restrict__ out)
{
    __shared__ float w[4][128];
    int tid = threadIdx.x;
    for (int idx = tid; idx < 512; idx += 128) w[idx >> 7][idx & 127] = Wfc[idx];
    __syncthreads();
    int b = blockIdx.x * 128 + tid;
    float s[4];
    #pragma unroll
    for (int cc = 0; cc < 4; ++cc) s[cc] = bfc[cc];
    #pragma unroll 4
    for (int k = 0; k < 128; ++k) {
        float h = g_h2last[b * 128 + k];
        #pragma unroll
        for (int cc = 0; cc < 4; ++cc) s[cc] = fmaf(h, w[cc][k], s[cc]);
    }
    #pragma unroll
    for (int cc = 0; cc < 4; ++cc) out[b * 4 + cc] = s[cc];
}

extern "C" void kernel_launch(void* const* d_in, const int* in_sizes, int n_in,
                              void* d_out, int out_size)
{
    (void)in_sizes; (void)n_in; (void)out_size;
    const float* x    = (const float*)d_in[0];
    const float* Wih0 = (const float*)d_in[1];
    const float* Whh0 = (const float*)d_in[2];
    const float* bih0 = (const float*)d_in[3];
    const float* bhh0 = (const float*)d_in[4];
    const float* Wih1 = (const float*)d_in[5];
    const float* Whh1 = (const float*)d_in[6];
    const float* bih1 = (const float*)d_in[7];
    const float* bhh1 = (const float*)d_in[8];
    const float* Wfc  = (const float*)d_in[9];
    const float* bfc  = (const float*)d_in[10];
    float* out = (float*)d_out;

    // smem: max over layers (layer1: RW=512 -> ROWB=2064)
    const int ROWB1 = 512 * 4 + 16;
    const int SMEM  = BCL * ROWB1 + 4 * BCL * PSTR * 4 + 512 + 16 + 256;   // ~134.5 KB

    cudaFuncSetAttribute((const void*)lstm_fused,
                         cudaFuncAttributeMaxDynamicSharedMemorySize, SMEM);

    zero_flags_kernel<<<1, 32>>>();
    lstm_fused<<<2 * NCL * CLUSTER_N, THREADS, SMEM>>>(
        x, Wih0, Whh0, bih0, bhh0, Wih1, Whh1, bih1, bhh1);
    fc_kernel<<<4, 128>>>(Wfc, bfc, out);
}